// round 2
// baseline (speedup 1.0000x reference)
#include <cuda_runtime.h>

// CircularNN: 3 sparse gather layers (K=2,4,8) + exact GELU, then 784->10 FC + softmax.
// B=65536 samples, D=784 features.
//
// Strategy: 1 block = 32 samples. lane <-> sample mapping, SMEM activation
// buffers padded to stride 785 (gcd(785 mod 32, 32) = 1 -> gathers are
// bank-conflict-free since the gather index is warp-uniform).
// Weights/indices are warp-uniform LDGs (L1/L2 resident), vectorized.

#define D     784
#define PAD   785
#define S     32      // samples per block
#define NW    16      // warps per block
#define NT    512     // threads per block
#define NCLS  10
#define NPW   (D / NW)  // 49 outputs per warp per layer

__device__ __forceinline__ float gelu_exact(float a) {
    return 0.5f * a * (1.0f + erff(a * 0.70710678118654752f));
}

template<int K>
__device__ __forceinline__ void sparse_layer_f(
    const float* __restrict__ src, float* __restrict__ dst,
    const int* __restrict__ idx, const float* __restrict__ w,
    const float* __restrict__ bias, int lane, int warp)
{
    const float* srow = src + lane * PAD;
    float*       drow = dst + lane * PAD;
    const int n0 = warp * NPW;
    #pragma unroll 1
    for (int n = n0; n < n0 + NPW; ++n) {
        float acc = __ldg(bias + n);
        if constexpr (K == 2) {
            int2   j  = __ldg((const int2*)(idx) + n);
            float2 ww = __ldg((const float2*)(w) + n);
            acc = fmaf(ww.x, srow[j.x], acc);
            acc = fmaf(ww.y, srow[j.y], acc);
        } else if constexpr (K == 4) {
            int4   j  = __ldg((const int4*)(idx) + n);
            float4 ww = __ldg((const float4*)(w) + n);
            acc = fmaf(ww.x, srow[j.x], acc);
            acc = fmaf(ww.y, srow[j.y], acc);
            acc = fmaf(ww.z, srow[j.z], acc);
            acc = fmaf(ww.w, srow[j.w], acc);
        } else {  // K == 8
            int4   ja = __ldg((const int4*)(idx) + 2 * n);
            int4   jb = __ldg((const int4*)(idx) + 2 * n + 1);
            float4 wa = __ldg((const float4*)(w) + 2 * n);
            float4 wb = __ldg((const float4*)(w) + 2 * n + 1);
            acc = fmaf(wa.x, srow[ja.x], acc);
            acc = fmaf(wa.y, srow[ja.y], acc);
            acc = fmaf(wa.z, srow[ja.z], acc);
            acc = fmaf(wa.w, srow[ja.w], acc);
            acc = fmaf(wb.x, srow[jb.x], acc);
            acc = fmaf(wb.y, srow[jb.y], acc);
            acc = fmaf(wb.z, srow[jb.z], acc);
            acc = fmaf(wb.w, srow[jb.w], acc);
        }
        drow[n] = gelu_exact(acc);
    }
}

extern __shared__ float smem[];

__global__ __launch_bounds__(NT, 1)
void circnn_kernel(const float* __restrict__ x,
                   const int*   __restrict__ idx1, const float* __restrict__ w1, const float* __restrict__ b1,
                   const int*   __restrict__ idx2, const float* __restrict__ w2, const float* __restrict__ b2,
                   const int*   __restrict__ idx3, const float* __restrict__ w3, const float* __restrict__ b3,
                   const float* __restrict__ fc_w, const float* __restrict__ fc_b,
                   float* __restrict__ out, int B)
{
    float* bufA = smem;                         // S*PAD
    float* bufB = smem + S * PAD;               // S*PAD
    float* part = smem + 2 * S * PAD;           // NW*S*NCLS

    const int tid  = threadIdx.x;
    const int lane = tid & 31;
    const int warp = tid >> 5;
    const long base = (long)blockIdx.x * S;

    // --- load 32 sample rows of x into bufA (coalesced) ---
    for (int i = tid; i < S * D; i += NT) {
        int s = i / D;
        int d = i - s * D;
        long gs = base + s;
        bufA[s * PAD + d] = (gs < B) ? x[gs * (long)D + d] : 0.0f;
    }
    __syncthreads();

    sparse_layer_f<2>(bufA, bufB, idx1, w1, b1, lane, warp);
    __syncthreads();
    sparse_layer_f<4>(bufB, bufA, idx2, w2, b2, lane, warp);
    __syncthreads();
    sparse_layer_f<8>(bufA, bufB, idx3, w3, b3, lane, warp);
    __syncthreads();

    // --- FC partials: lane = sample, warp owns a strided set of 4-wide n-chunks ---
    {
        float acc[NCLS];
        #pragma unroll
        for (int c = 0; c < NCLS; ++c) acc[c] = 0.0f;

        const float* hrow = bufB + lane * PAD;
        for (int ch = warp; ch < D / 4; ch += NW) {
            const int n = ch * 4;
            float h0 = hrow[n + 0];
            float h1 = hrow[n + 1];
            float h2 = hrow[n + 2];
            float h3 = hrow[n + 3];
            #pragma unroll
            for (int c = 0; c < NCLS; ++c) {
                float4 wv = __ldg((const float4*)(fc_w + c * D + n));
                acc[c] = fmaf(h0, wv.x,
                         fmaf(h1, wv.y,
                         fmaf(h2, wv.z,
                         fmaf(h3, wv.w, acc[c]))));
            }
        }
        float* p = part + warp * (S * NCLS) + lane * NCLS;
        #pragma unroll
        for (int c = 0; c < NCLS; ++c) p[c] = acc[c];
    }
    __syncthreads();

    // --- deterministic reduction + softmax: thread s handles sample s ---
    if (tid < S) {
        const int s = tid;
        const long gs = base + s;
        if (gs < B) {
            float l[NCLS];
            #pragma unroll
            for (int c = 0; c < NCLS; ++c) l[c] = __ldg(fc_b + c);
            for (int w = 0; w < NW; ++w) {
                const float* p = part + w * (S * NCLS) + s * NCLS;
                #pragma unroll
                for (int c = 0; c < NCLS; ++c) l[c] += p[c];
            }
            float m = l[0];
            #pragma unroll
            for (int c = 1; c < NCLS; ++c) m = fmaxf(m, l[c]);
            float sum = 0.0f;
            #pragma unroll
            for (int c = 0; c < NCLS; ++c) { l[c] = expf(l[c] - m); sum += l[c]; }
            const float inv = 1.0f / sum;
            float* o = out + gs * NCLS;
            #pragma unroll
            for (int c = 0; c < NCLS; ++c) o[c] = l[c] * inv;
        }
    }
}

extern "C" void kernel_launch(void* const* d_in, const int* in_sizes, int n_in,
                              void* d_out, int out_size)
{
    const float* x    = (const float*)d_in[0];
    const int*   idx1 = (const int*)  d_in[1];
    const float* w1   = (const float*)d_in[2];
    const float* b1   = (const float*)d_in[3];
    const int*   idx2 = (const int*)  d_in[4];
    const float* w2   = (const float*)d_in[5];
    const float* b2   = (const float*)d_in[6];
    const int*   idx3 = (const int*)  d_in[7];
    const float* w3   = (const float*)d_in[8];
    const float* b3   = (const float*)d_in[9];
    const float* fc_w = (const float*)d_in[10];
    const float* fc_b = (const float*)d_in[11];
    float* out = (float*)d_out;

    const int B = in_sizes[0] / D;
    const int grid = (B + S - 1) / S;
    const int smem_bytes = (2 * S * PAD + NW * S * NCLS) * (int)sizeof(float);  // 221440

    cudaFuncSetAttribute(circnn_kernel,
                         cudaFuncAttributeMaxDynamicSharedMemorySize, smem_bytes);

    circnn_kernel<<<grid, NT, smem_bytes>>>(x, idx1, w1, b1, idx2, w2, b2,
                                            idx3, w3, b3, fc_w, fc_b, out, B);
}

// round 3
// speedup vs baseline: 1.3991x; 1.3991x over previous
#include <cuda_runtime.h>

// CircularNN: 3 sparse gather layers (K=2,4,8) + exact GELU, then 784->10 FC + softmax.
// B=65536, D=784.
//
// R2: S=16 samples/CTA, 512 threads, smem ~100.5KB -> 2 CTAs/SM (32 warps/SM).
// lane = {f_off:1, s:4}: each warp instruction covers 2 features x 16 samples.
// Stride 785 (== 17 mod 32) keeps per-half-warp gathers on 16 distinct banks.

#define D     784
#define PAD   785
#define S     16      // samples per block
#define NW    16      // warps per block
#define NT    512
#define NCLS  10
#define NPW   49      // features per warp per layer
#define NITER 25      // feature-pair iterations (covers 49 = 24*2 + 1)

__device__ __forceinline__ float gelu_exact(float a) {
    return 0.5f * a * (1.0f + erff(a * 0.70710678118654752f));
}

template<int K>
__device__ __forceinline__ void sparse_layer_f(
    const float* __restrict__ src, float* __restrict__ dst,
    const int* __restrict__ idx, const float* __restrict__ w,
    const float* __restrict__ bias, int s, int fo, int warp)
{
    const float* srow = src + s * PAD;
    float*       drow = dst + s * PAD;
    const int n0 = warp * NPW;
    #pragma unroll 1
    for (int i = 0; i < NITER; ++i) {
        const int o = 2 * i + fo;
        const bool valid = (o < NPW);
        const int f = n0 + (valid ? o : 0);
        float acc = __ldg(bias + f);
        if constexpr (K == 2) {
            int2   j  = __ldg((const int2*)(idx) + f);
            float2 ww = __ldg((const float2*)(w) + f);
            acc = fmaf(ww.x, srow[j.x], acc);
            acc = fmaf(ww.y, srow[j.y], acc);
        } else if constexpr (K == 4) {
            int4   j  = __ldg((const int4*)(idx) + f);
            float4 ww = __ldg((const float4*)(w) + f);
            float t  = ww.y * srow[j.y];
            acc = fmaf(ww.x, srow[j.x], acc);
            t   = fmaf(ww.w, srow[j.w], t);
            acc = fmaf(ww.z, srow[j.z], acc);
            acc += t;
        } else {  // K == 8, two accumulation trees
            int4   ja = __ldg((const int4*)(idx) + 2 * f);
            int4   jb = __ldg((const int4*)(idx) + 2 * f + 1);
            float4 wa = __ldg((const float4*)(w) + 2 * f);
            float4 wb = __ldg((const float4*)(w) + 2 * f + 1);
            float t = wa.y * srow[ja.y];
            acc = fmaf(wa.x, srow[ja.x], acc);
            t   = fmaf(wa.w, srow[ja.w], t);
            acc = fmaf(wa.z, srow[ja.z], acc);
            t   = fmaf(wb.y, srow[jb.y], t);
            acc = fmaf(wb.x, srow[jb.x], acc);
            t   = fmaf(wb.w, srow[jb.w], t);
            acc = fmaf(wb.z, srow[jb.z], acc);
            acc += t;
        }
        float g = gelu_exact(acc);
        if (valid) drow[f] = g;
    }
}

extern __shared__ float smem[];

__global__ __launch_bounds__(NT, 2)
void circnn_kernel(const float* __restrict__ x,
                   const int*   __restrict__ idx1, const float* __restrict__ w1, const float* __restrict__ b1,
                   const int*   __restrict__ idx2, const float* __restrict__ w2, const float* __restrict__ b2,
                   const int*   __restrict__ idx3, const float* __restrict__ w3, const float* __restrict__ b3,
                   const float* __restrict__ fc_w, const float* __restrict__ fc_b,
                   float* __restrict__ out, int B)
{
    float* bufA = smem;               // S*PAD
    float* bufB = smem + S * PAD;     // S*PAD
    float* part = smem;               // aliases bufA (dead after layer3): NW*S*NCLS = 2560 floats

    const int tid  = threadIdx.x;
    const int lane = tid & 31;
    const int warp = tid >> 5;
    const int s    = lane & 15;       // sample within block
    const int fo   = lane >> 4;       // feature offset within pair
    const long base = (long)blockIdx.x * S;

    // --- load 16 sample rows of x (float4, coalesced) ---
    {
        const float4* x4 = (const float4*)(x + base * (long)D);
        for (int i = tid; i < S * (D / 4); i += NT) {
            int s0 = i / (D / 4);
            int d4 = i - s0 * (D / 4);
            float4 v = __ldg(x4 + i);
            float* p = bufA + s0 * PAD + d4 * 4;
            p[0] = v.x; p[1] = v.y; p[2] = v.z; p[3] = v.w;
        }
    }
    __syncthreads();

    sparse_layer_f<2>(bufA, bufB, idx1, w1, b1, s, fo, warp);
    __syncthreads();
    sparse_layer_f<4>(bufB, bufA, idx2, w2, b2, s, fo, warp);
    __syncthreads();
    sparse_layer_f<8>(bufA, bufB, idx3, w3, b3, s, fo, warp);
    __syncthreads();

    // --- FC partials: thread = (sample s, chunk residue tid>>4), float4 weights ---
    {
        float acc[NCLS];
        #pragma unroll
        for (int c = 0; c < NCLS; ++c) acc[c] = 0.0f;

        const float* hrow = bufB + s * PAD;
        const int chunk0 = tid >> 4;                 // 0..31
        for (int c4 = chunk0; c4 < D / 4; c4 += 32) {
            const int f = c4 * 4;
            float h0 = hrow[f + 0];
            float h1 = hrow[f + 1];
            float h2 = hrow[f + 2];
            float h3 = hrow[f + 3];
            #pragma unroll
            for (int c = 0; c < NCLS; ++c) {
                float4 wv = __ldg((const float4*)(fc_w + c * D) + c4);
                acc[c] = fmaf(h0, wv.x,
                         fmaf(h1, wv.y,
                         fmaf(h2, wv.z,
                         fmaf(h3, wv.w, acc[c]))));
            }
        }
        // merge the two half-warps (same s, different chunk residues)
        #pragma unroll
        for (int c = 0; c < NCLS; ++c)
            acc[c] += __shfl_down_sync(0xffffffffu, acc[c], 16);

        __syncthreads();   // bufA fully dead for everyone before aliasing as `part`
        if (fo == 0) {
            float* p = part + (warp * S + s) * NCLS;
            #pragma unroll
            for (int c = 0; c < NCLS; ++c) p[c] = acc[c];
        }
    }
    __syncthreads();

    // --- deterministic reduction + softmax: thread t handles sample t ---
    if (tid < S) {
        const long gs = base + tid;
        if (gs < B) {
            float l[NCLS];
            #pragma unroll
            for (int c = 0; c < NCLS; ++c) l[c] = __ldg(fc_b + c);
            for (int w = 0; w < NW; ++w) {
                const float* p = part + (w * S + tid) * NCLS;
                #pragma unroll
                for (int c = 0; c < NCLS; ++c) l[c] += p[c];
            }
            float m = l[0];
            #pragma unroll
            for (int c = 1; c < NCLS; ++c) m = fmaxf(m, l[c]);
            float sum = 0.0f;
            #pragma unroll
            for (int c = 0; c < NCLS; ++c) { l[c] = expf(l[c] - m); sum += l[c]; }
            const float inv = 1.0f / sum;
            float* o = out + gs * NCLS;
            #pragma unroll
            for (int c = 0; c < NCLS; ++c) o[c] = l[c] * inv;
        }
    }
}

extern "C" void kernel_launch(void* const* d_in, const int* in_sizes, int n_in,
                              void* d_out, int out_size)
{
    const float* x    = (const float*)d_in[0];
    const int*   idx1 = (const int*)  d_in[1];
    const float* w1   = (const float*)d_in[2];
    const float* b1   = (const float*)d_in[3];
    const int*   idx2 = (const int*)  d_in[4];
    const float* w2   = (const float*)d_in[5];
    const float* b2   = (const float*)d_in[6];
    const int*   idx3 = (const int*)  d_in[7];
    const float* w3   = (const float*)d_in[8];
    const float* b3   = (const float*)d_in[9];
    const float* fc_w = (const float*)d_in[10];
    const float* fc_b = (const float*)d_in[11];
    float* out = (float*)d_out;

    const int B = in_sizes[0] / D;
    const int grid = (B + S - 1) / S;
    const int smem_bytes = 2 * S * PAD * (int)sizeof(float);  // 100,480

    cudaFuncSetAttribute(circnn_kernel,
                         cudaFuncAttributeMaxDynamicSharedMemorySize, smem_bytes);

    circnn_kernel<<<grid, NT, smem_bytes>>>(x, idx1, w1, b1, idx2, w2, b2,
                                            idx3, w3, b3, fc_w, fc_b, out, B);
}